// round 15
// baseline (speedup 1.0000x reference)
#include <cuda_runtime.h>
#include <cuda_fp16.h>
#include <cstdint>

// ---------------------------------------------------------------------------
// bwd_mpgnn: 6-level GNN stack. Every matmul is C = tanh(A @ W^T + b) with
// residuals folded into producer epilogues. Operands pre-split into FP16
// hi/lo planes. GEMM = cp.async(2-stage) -> ldmatrix -> mma.sync:
//   pass1: hi*hi  -> f32 accumulators  (mma f32.f16.f16.f32)
//   pass2: lo*hi  -> f16 accumulators  (mma f16.f16.f16.f16)
//   pass3: hi*lo  -> same f16 accumulators
// corrections are ~2^-11 of main -> fp16 accumulation injects ~2^-22.
// 2 CTAs/SM, 2-job batched launches (round-12 schedule).
// ---------------------------------------------------------------------------

#define NN 32768
#define PAD 40                        // smem row stride in fp16 elems (conflict-free ldmatrix)
#define TILE_BYTES (128 * PAD * 2)    // 10240 B per 128x32 plane
#define STAGES 2
#define SMEM_BYTES (STAGES * 4 * TILE_BYTES)   // 81920 B -> 2 CTAs/SM

typedef __half hf;

// ---------------- weight / input split planes ------------------------------
__device__ hf g_WeH[8192],      g_WeL[8192];
__device__ hf g_fH[6 * NN * 32], g_fL[6 * NN * 32];
__device__ hf g_s1H[786432], g_s1L[786432];
__device__ hf g_s2H[786432], g_s2L[786432];
__device__ hf g_s3H[786432], g_s3L[786432];
__device__ hf g_c1H[1572864], g_c1L[1572864];
__device__ hf g_c2H[1572864], g_c2L[1572864];
__device__ hf g_c3H[786432],  g_c3L[786432];

// ---------------- activation planes ----------------------------------------
__device__ hf g_PAh[NN * 512], g_PAl[NN * 512];
__device__ hf g_PBh[NN * 512], g_PBl[NN * 512];
__device__ hf g_X2h[NN * 512], g_X2l[NN * 512];
__device__ hf g_Eh [NN * 256], g_El [NN * 256];
__device__ hf g_T0h[NN * 256], g_T0l[NN * 256];
__device__ hf g_T1h[NN * 256], g_T1l[NN * 256];
__device__ hf g_T2h[NN * 256], g_T2l[NN * 256];
__device__ hf g_Mh [NN * 256], g_Ml [NN * 256];
__device__ hf g_U0h[NN * 256], g_U0l[NN * 256];
__device__ hf g_U1h[NN * 256], g_U1l[NN * 256];
__device__ hf g_U2h[NN * 256], g_U2l[NN * 256];
__device__ float g_Ef [NN * 256];
__device__ float g_T0f[NN * 256];
__device__ float g_Mf [NN * 256];
__device__ float g_U0f[NN * 256];
__device__ float g_X2f[NN * 512];

// ---------------- accurate rational tanh (XLA/Eigen) -----------------------
__device__ __forceinline__ float fast_tanh(float x) {
    const float c = 7.90531110763549805f;
    x = fminf(fmaxf(x, -c), c);
    const float x2 = x * x;
    float p = fmaf(x2, -2.76076847742355e-16f, 2.00018790482477e-13f);
    p = fmaf(x2, p, -8.60467152213735e-11f);
    p = fmaf(x2, p, 5.12229709037114e-08f);
    p = fmaf(x2, p, 1.48572235717979e-05f);
    p = fmaf(x2, p, 6.37261928875436e-04f);
    p = fmaf(x2, p, 4.89352455891786e-03f);
    p = x * p;
    float q = fmaf(x2, 1.19825839466702e-06f, 1.18534705686654e-04f);
    q = fmaf(x2, q, 2.26843463243900e-03f);
    q = fmaf(x2, q, 4.89352518554385e-03f);
    return p / q;
}

// ---------------- mma / ldmatrix helpers -----------------------------------
__device__ __forceinline__ void ldm_x4(uint32_t a, uint32_t& r0, uint32_t& r1,
                                       uint32_t& r2, uint32_t& r3) {
    asm volatile("ldmatrix.sync.aligned.m8n8.x4.shared.b16 {%0,%1,%2,%3}, [%4];\n"
                 : "=r"(r0), "=r"(r1), "=r"(r2), "=r"(r3) : "r"(a));
}
// fp16 inputs, fp32 accumulate (main pass)
__device__ __forceinline__ void mma_f32(float* c, const uint32_t* a, const uint32_t* b) {
    asm volatile("mma.sync.aligned.m16n8k16.row.col.f32.f16.f16.f32 "
                 "{%0,%1,%2,%3}, {%4,%5,%6,%7}, {%8,%9}, {%0,%1,%2,%3};\n"
                 : "+f"(c[0]), "+f"(c[1]), "+f"(c[2]), "+f"(c[3])
                 : "r"(a[0]), "r"(a[1]), "r"(a[2]), "r"(a[3]), "r"(b[0]), "r"(b[1]));
}
// fp16 inputs, fp16 accumulate (correction passes)
__device__ __forceinline__ void mma_f16(uint32_t* c, const uint32_t* a, const uint32_t* b) {
    asm volatile("mma.sync.aligned.m16n8k16.row.col.f16.f16.f16.f16 "
                 "{%0,%1}, {%2,%3,%4,%5}, {%6,%7}, {%0,%1};\n"
                 : "+r"(c[0]), "+r"(c[1])
                 : "r"(a[0]), "r"(a[1]), "r"(a[2]), "r"(a[3]), "r"(b[0]), "r"(b[1]));
}
__device__ __forceinline__ uint32_t pack2(hf a, hf b) {
    return ((uint32_t)__half_as_ushort(b) << 16) | (uint32_t)__half_as_ushort(a);
}
__device__ __forceinline__ uint32_t split_hi(float2 v, uint32_t& lo) {
    hf h0 = __float2half_rn(v.x), h1 = __float2half_rn(v.y);
    hf l0 = __float2half_rn(v.x - __half2float(h0));
    hf l1 = __float2half_rn(v.y - __half2float(h1));
    lo = pack2(l0, l1);
    return pack2(h0, h1);
}

// ---------------- job descriptor for batched GEMM launches -----------------
struct GJob {
    const hf *Ah, *Al, *Wh, *Wl;
    const float *bias, *R;
    float *Cf;
    hf *Ch, *Cl;
    int lda, ldw, ldr, Rcols, ldc, K;
};

// ---------------------------------------------------------------------------
// C = tanh(A @ W^T + bias) [+R on cols<Rcols, added after tanh]
// Two jobs per launch: blockIdx.y < split -> j0, else j1 (nBase rebased).
// BM=BN=128, BK=32, 256 threads (8 warps 2x4), warp tile 64x32, 2-stage cp.async.
// ---------------------------------------------------------------------------
__global__ __launch_bounds__(256, 2) void gemm_tanh(GJob j0, GJob j1, int split)
{
    extern __shared__ char smem[];
    const bool s1 = (int)blockIdx.y >= split;
    const hf* __restrict__ Ah = s1 ? j1.Ah : j0.Ah;
    const hf* __restrict__ Al = s1 ? j1.Al : j0.Al;
    const hf* __restrict__ Wh = s1 ? j1.Wh : j0.Wh;
    const hf* __restrict__ Wl = s1 ? j1.Wl : j0.Wl;
    const float* __restrict__ bias = s1 ? j1.bias : j0.bias;
    const float* __restrict__ R = s1 ? j1.R : j0.R;
    float* __restrict__ Cf = s1 ? j1.Cf : j0.Cf;
    hf* __restrict__ Ch = s1 ? j1.Ch : j0.Ch;
    hf* __restrict__ Cl = s1 ? j1.Cl : j0.Cl;
    const int lda = s1 ? j1.lda : j0.lda;
    const int ldw = s1 ? j1.ldw : j0.ldw;
    const int ldr = s1 ? j1.ldr : j0.ldr;
    const int Rcols = s1 ? j1.Rcols : j0.Rcols;
    const int ldc = s1 ? j1.ldc : j0.ldc;
    const int K  = s1 ? j1.K : j0.K;

    const int tid  = threadIdx.x;
    const int lane = tid & 31;
    const int wid  = tid >> 5;
    const int wm   = wid >> 2;   // 0..1
    const int wn   = wid & 3;    // 0..3
    const int mBase = blockIdx.x * 128;
    const int nBase = (s1 ? (int)blockIdx.y - split : (int)blockIdx.y) * 128;
    const uint32_t sb = (uint32_t)__cvta_generic_to_shared(smem);

    float acc[4][4][4];
    uint32_t acc16[4][4][2];   // packed half2 correction accumulators
#pragma unroll
    for (int i = 0; i < 4; i++)
#pragma unroll
        for (int j = 0; j < 4; j++) {
#pragma unroll
            for (int k = 0; k < 4; k++) acc[i][j][k] = 0.f;
            acc16[i][j][0] = 0u; acc16[i][j][1] = 0u;
        }

    const int T = K >> 5;
    const int seg   = tid & 3;           // 16B segment within 64B row chunk
    const int rhalf = tid >> 2;          // 0..63

    auto issue = [&](int t) {
        const int k0 = (t << 5) + seg * 8;
        const uint32_t stb = sb + (uint32_t)((t & 1) * 4 * TILE_BYTES);
#pragma unroll
        for (int i = 0; i < 8; i++) {
            const int plane = i >> 1;                 // 0:Ah 1:Al 2:Wh 3:Wl
            const int row   = (i & 1) * 64 + rhalf;   // 0..127
            const uint32_t dst = stb + (uint32_t)(plane * TILE_BYTES + row * (PAD * 2) + seg * 16);
            const hf* src;
            if      (plane == 0) src = Ah + (size_t)(mBase + row) * lda + k0;
            else if (plane == 1) src = Al + (size_t)(mBase + row) * lda + k0;
            else if (plane == 2) src = Wh + (size_t)(nBase + row) * ldw + k0;
            else                 src = Wl + (size_t)(nBase + row) * ldw + k0;
            asm volatile("cp.async.cg.shared.global [%0], [%1], 16;\n" :: "r"(dst), "l"(src));
        }
    };

    const int r16  = ((lane >> 3) & 1) * 8 + (lane & 7);
    const int kofA = (lane >> 4) * 8;
    const int bRow = ((lane >> 4) & 1) * 8 + (lane & 7);
    const int kofB = ((lane >> 3) & 1) * 8;

    auto compute = [&](int s) {
        const uint32_t ab = sb + (uint32_t)(s * 4 * TILE_BYTES);
        const uint32_t bb = ab + 2 * TILE_BYTES;
#pragma unroll
        for (int ks = 0; ks < 2; ks++) {
            uint32_t a1[4][4], bh[4][2];
            // ---- hi fragments ----
#pragma unroll
            for (int mf = 0; mf < 4; mf++) {
                const uint32_t addr = ab +
                    (uint32_t)(((wm * 64 + mf * 16 + r16) * PAD + ks * 16 + kofA) * 2);
                ldm_x4(addr, a1[mf][0], a1[mf][1], a1[mf][2], a1[mf][3]);
            }
#pragma unroll
            for (int p = 0; p < 2; p++) {
                const uint32_t addr = bb +
                    (uint32_t)(((wn * 32 + p * 16 + bRow) * PAD + ks * 16 + kofB) * 2);
                ldm_x4(addr, bh[2 * p][0], bh[2 * p][1], bh[2 * p + 1][0], bh[2 * p + 1][1]);
            }
            // pass1: hi*hi -> f32
#pragma unroll
            for (int mf = 0; mf < 4; mf++)
#pragma unroll
                for (int nf = 0; nf < 4; nf++) mma_f32(acc[mf][nf], a1[mf], bh[nf]);
            // pass2: lo*hi -> f16 acc (a2 staged per-mf, low reg pressure)
#pragma unroll
            for (int mf = 0; mf < 4; mf++) {
                uint32_t a2[4];
                const uint32_t addr = ab + TILE_BYTES +
                    (uint32_t)(((wm * 64 + mf * 16 + r16) * PAD + ks * 16 + kofA) * 2);
                ldm_x4(addr, a2[0], a2[1], a2[2], a2[3]);
#pragma unroll
                for (int nf = 0; nf < 4; nf++) mma_f16(acc16[mf][nf], a2, bh[nf]);
            }
            // pass3: hi*lo -> f16 acc (bl staged per-pair)
#pragma unroll
            for (int p = 0; p < 2; p++) {
                uint32_t bl[2][2];
                const uint32_t addr = bb + TILE_BYTES +
                    (uint32_t)(((wn * 32 + p * 16 + bRow) * PAD + ks * 16 + kofB) * 2);
                ldm_x4(addr, bl[0][0], bl[0][1], bl[1][0], bl[1][1]);
#pragma unroll
                for (int mf = 0; mf < 4; mf++) {
                    mma_f16(acc16[mf][2 * p],     a1[mf], bl[0]);
                    mma_f16(acc16[mf][2 * p + 1], a1[mf], bl[1]);
                }
            }
        }
    };

    issue(0);
    asm volatile("cp.async.commit_group;\n" ::: "memory");
    for (int t = 0; t < T; t++) {
        asm volatile("cp.async.wait_group 0;\n" ::: "memory");
        __syncthreads();
        if (t + 1 < T) {
            issue(t + 1);
            asm volatile("cp.async.commit_group;\n" ::: "memory");
        }
        compute(t & 1);
    }

    // epilogue: main + corrections, bias + tanh (+residual), write outputs
#pragma unroll
    for (int mf = 0; mf < 4; mf++) {
        const int r0 = mBase + wm * 64 + mf * 16 + (lane >> 2);
#pragma unroll
        for (int nf = 0; nf < 4; nf++) {
            const int c0 = nBase + wn * 32 + nf * 8 + (lane & 3) * 2;
            const float b0 = __ldg(bias + c0), b1 = __ldg(bias + c0 + 1);
            const float2 k0 = __half22float2(*(__half2*)&acc16[mf][nf][0]);
            const float2 k1 = __half22float2(*(__half2*)&acc16[mf][nf][1]);
            float2 v0 = make_float2(fast_tanh(acc[mf][nf][0] + k0.x + b0),
                                    fast_tanh(acc[mf][nf][1] + k0.y + b1));
            float2 v1 = make_float2(fast_tanh(acc[mf][nf][2] + k1.x + b0),
                                    fast_tanh(acc[mf][nf][3] + k1.y + b1));
            if (R != nullptr && c0 < Rcols) {
                const float2 ra = *(const float2*)(R + (size_t)r0 * ldr + c0);
                const float2 rb = *(const float2*)(R + (size_t)(r0 + 8) * ldr + c0);
                v0.x += ra.x; v0.y += ra.y;
                v1.x += rb.x; v1.y += rb.y;
            }
            const size_t o0 = (size_t)r0 * ldc + c0;
            const size_t o1 = (size_t)(r0 + 8) * ldc + c0;
            if (Cf != nullptr) {
                *(float2*)(Cf + o0) = v0;
                *(float2*)(Cf + o1) = v1;
            }
            if (Ch != nullptr) {
                uint32_t lo0, lo1;
                const uint32_t hi0 = split_hi(v0, lo0);
                const uint32_t hi1 = split_hi(v1, lo1);
                *(uint32_t*)(Ch + o0) = hi0;  *(uint32_t*)(Cl + o0) = lo0;
                *(uint32_t*)(Ch + o1) = hi1;  *(uint32_t*)(Cl + o1) = lo1;
            }
        }
    }
}

// ---------------- fused fp32 -> fp16 hi/lo split over 8 tensors ------------
struct SplitJobs {
    const float* src[8];
    hf* h[8];
    hf* l[8];
    int n4[8];
    int boff[8];
};
__global__ __launch_bounds__(256) void split_all(SplitJobs J) {
    const int b = blockIdx.x;
    int j = 0;
#pragma unroll
    for (int i = 1; i < 8; i++)
        if (b >= J.boff[i]) j = i;
    const int i4 = (b - J.boff[j]) * 256 + threadIdx.x;
    if (i4 >= J.n4[j]) return;
    const float4 v = *(const float4*)(J.src[j] + (size_t)i4 * 4);
    uint32_t lo0, lo1;
    const uint32_t hi0 = split_hi(make_float2(v.x, v.y), lo0);
    const uint32_t hi1 = split_hi(make_float2(v.z, v.w), lo1);
    *(uint2*)(J.h[j] + (size_t)i4 * 4) = make_uint2(hi0, hi1);
    *(uint2*)(J.l[j] + (size_t)i4 * 4) = make_uint2(lo0, lo1);
}

// msgs[n,:] = sum_{k<8} src[idx[n,k], :] ; writes fp32 + split planes
__global__ __launch_bounds__(256) void gather_sum(
    const float* __restrict__ src, const int* __restrict__ idx,
    float* __restrict__ dstf, hf* __restrict__ dsth, hf* __restrict__ dstl)
{
    const int node = blockIdx.x * 4 + (threadIdx.x >> 6);
    const int lane = threadIdx.x & 63;
    const int* ip = idx + node * 8;
    float4 s = make_float4(0.f, 0.f, 0.f, 0.f);
#pragma unroll
    for (int k = 0; k < 8; k++) {
        const float4 v = *(const float4*)(src + (size_t)ip[k] * 256 + lane * 4);
        s.x += v.x; s.y += v.y; s.z += v.z; s.w += v.w;
    }
    const size_t o = (size_t)node * 256 + lane * 4;
    *(float4*)(dstf + o) = s;
    uint32_t lo0, lo1;
    const uint32_t hi0 = split_hi(make_float2(s.x, s.y), lo0);
    const uint32_t hi1 = split_hi(make_float2(s.z, s.w), lo1);
    *(uint2*)(dsth + o) = make_uint2(hi0, hi1);
    *(uint2*)(dstl + o) = make_uint2(lo0, lo1);
}

extern "C" void kernel_launch(void* const* d_in, const int* in_sizes, int n_in,
                              void* d_out, int out_size)
{
    const float* feats = (const float*)d_in[0];
    const int*   pred  = (const int*)  d_in[1];
    const float* WeF   = (const float*)d_in[2];
    const float* be    = (const float*)d_in[3];
    const float* rsW1  = (const float*)d_in[4];
    const float* rsb1  = (const float*)d_in[5];
    const float* rsW2  = (const float*)d_in[6];
    const float* rsb2  = (const float*)d_in[7];
    const float* rsW3  = (const float*)d_in[8];
    const float* rsb3  = (const float*)d_in[9];
    const float* rcW1  = (const float*)d_in[10];
    const float* rcb1  = (const float*)d_in[11];
    const float* rcW2  = (const float*)d_in[12];
    const float* rcb2  = (const float*)d_in[13];
    const float* rcW3  = (const float*)d_in[14];
    const float* rcb3  = (const float*)d_in[15];
    float* out = (float*)d_out;

    hf *WeH,*WeL,*fH,*fL,*s1H,*s1L,*s2H,*s2L,*s3H,*s3L,*c1H,*c1L,*c2H,*c2L,*c3H,*c3L;
    hf *PAh,*PAl,*PBh,*PBl,*X2h,*X2l,*Eh,*El,*T0h,*T0l,*T1h,*T1l,*T2h,*T2l,*Mh,*Ml;
    hf *U0h,*U0l,*U1h,*U1l,*U2h,*U2l;
    float *Ef,*T0f,*Mf,*U0f,*X2f;
    cudaGetSymbolAddress((void**)&WeH, g_WeH); cudaGetSymbolAddress((void**)&WeL, g_WeL);
    cudaGetSymbolAddress((void**)&fH,  g_fH);  cudaGetSymbolAddress((void**)&fL,  g_fL);
    cudaGetSymbolAddress((void**)&s1H, g_s1H); cudaGetSymbolAddress((void**)&s1L, g_s1L);
    cudaGetSymbolAddress((void**)&s2H, g_s2H); cudaGetSymbolAddress((void**)&s2L, g_s2L);
    cudaGetSymbolAddress((void**)&s3H, g_s3H); cudaGetSymbolAddress((void**)&s3L, g_s3L);
    cudaGetSymbolAddress((void**)&c1H, g_c1H); cudaGetSymbolAddress((void**)&c1L, g_c1L);
    cudaGetSymbolAddress((void**)&c2H, g_c2H); cudaGetSymbolAddress((void**)&c2L, g_c2L);
    cudaGetSymbolAddress((void**)&c3H, g_c3H); cudaGetSymbolAddress((void**)&c3L, g_c3L);
    cudaGetSymbolAddress((void**)&PAh, g_PAh); cudaGetSymbolAddress((void**)&PAl, g_PAl);
    cudaGetSymbolAddress((void**)&PBh, g_PBh); cudaGetSymbolAddress((void**)&PBl, g_PBl);
    cudaGetSymbolAddress((void**)&X2h, g_X2h); cudaGetSymbolAddress((void**)&X2l, g_X2l);
    cudaGetSymbolAddress((void**)&Eh,  g_Eh);  cudaGetSymbolAddress((void**)&El,  g_El);
    cudaGetSymbolAddress((void**)&T0h, g_T0h); cudaGetSymbolAddress((void**)&T0l, g_T0l);
    cudaGetSymbolAddress((void**)&T1h, g_T1h); cudaGetSymbolAddress((void**)&T1l, g_T1l);
    cudaGetSymbolAddress((void**)&T2h, g_T2h); cudaGetSymbolAddress((void**)&T2l, g_T2l);
    cudaGetSymbolAddress((void**)&Mh,  g_Mh);  cudaGetSymbolAddress((void**)&Ml,  g_Ml);
    cudaGetSymbolAddress((void**)&U0h, g_U0h); cudaGetSymbolAddress((void**)&U0l, g_U0l);
    cudaGetSymbolAddress((void**)&U1h, g_U1h); cudaGetSymbolAddress((void**)&U1l, g_U1l);
    cudaGetSymbolAddress((void**)&U2h, g_U2h); cudaGetSymbolAddress((void**)&U2l, g_U2l);
    cudaGetSymbolAddress((void**)&Ef,  g_Ef);  cudaGetSymbolAddress((void**)&T0f, g_T0f);
    cudaGetSymbolAddress((void**)&Mf,  g_Mf);  cudaGetSymbolAddress((void**)&U0f, g_U0f);
    cudaGetSymbolAddress((void**)&X2f, g_X2f);

    cudaFuncSetAttribute(gemm_tanh, cudaFuncAttributeMaxDynamicSharedMemorySize, SMEM_BYTES);

    // one fused split launch for all weights + feats
    {
        SplitJobs J;
        const float* srcs[8] = {WeF, feats, rsW1, rsW2, rsW3, rcW1, rcW2, rcW3};
        hf* hs[8] = {WeH, fH, s1H, s2H, s3H, c1H, c2H, c3H};
        hf* ls[8] = {WeL, fL, s1L, s2L, s3L, c1L, c2L, c3L};
        const int ns[8] = {8192, 6 * NN * 32, 786432, 786432, 786432,
                           1572864, 1572864, 786432};
        int off = 0;
        for (int i = 0; i < 8; i++) {
            J.src[i] = srcs[i]; J.h[i] = hs[i]; J.l[i] = ls[i];
            J.n4[i] = ns[i] / 4; J.boff[i] = off;
            off += (J.n4[i] + 255) / 256;
        }
        split_all<<<off, 256>>>(J);
    }

    auto mk = [](const hf* Ah, const hf* Al, int lda,
                 const hf* Wh, const hf* Wl, int ldw,
                 const float* b, const float* R, int ldr, int Rcols,
                 float* Cf, hf* Ch, hf* Cl, int ldc, int K) {
        GJob j;
        j.Ah = Ah; j.Al = Al; j.Wh = Wh; j.Wl = Wl;
        j.bias = b; j.R = R; j.Cf = Cf; j.Ch = Ch; j.Cl = Cl;
        j.lda = lda; j.ldw = ldw; j.ldr = ldr; j.Rcols = Rcols; j.ldc = ldc; j.K = K;
        return j;
    };
    auto G1 = [&](GJob a, int Na) {
        dim3 grid(NN / 128, Na / 128);
        gemm_tanh<<<grid, 256, SMEM_BYTES>>>(a, a, Na / 128);
    };
    auto G2 = [&](GJob a, int Na, GJob b, int Nb) {
        dim3 grid(NN / 128, (Na + Nb) / 128);
        gemm_tanh<<<grid, 256, SMEM_BYTES>>>(a, b, Na / 128);
    };

    // boot: out[0] = embed(feats0)  ||  E = embed(feats1)
    G2(mk(fH, fL, 32, WeH, WeL, 32, be, nullptr, 0, 0,
          out, nullptr, nullptr, 256, 32), 256,
       mk(fH + (size_t)NN * 32, fL + (size_t)NN * 32, 32, WeH, WeL, 32, be,
          nullptr, 0, 0, Ef, Eh, El, 256, 32), 256);

    for (int l = 1; l < 6; l++) {
        const int d  = (l - 1 < 2) ? (l - 1) : 2;
        const int i1 = 3 + d, i2 = 9 + d, i3 = d, i4 = 6 + d;
        const int sA = 2 * d, sB = 2 * d + 1;

        gather_sum<<<NN / 4, 256>>>(out + (size_t)(l - 1) * NN * 256,
                                    pred + (size_t)(l - 1) * NN * 8, Mf, Mh, Ml);

        // pair1: big(i1) layer1 (E -> PA, K=256 zero-half skipped)  ||  sA layer1
        G2(mk(Eh, El, 256, c1H + (size_t)i1 * 262144, c1L + (size_t)i1 * 262144, 512,
              rcb1 + i1 * 512, nullptr, 0, 0, nullptr, PAh, PAl, 512, 256), 512,
           mk(Mh, Ml, 256, s1H + (size_t)sA * 65536, s1L + (size_t)sA * 65536, 256,
              rsb1 + sA * 256, nullptr, 0, 0, nullptr, U1h, U1l, 256, 256), 256);
        // pair2: big(i1) layer2 (+E residual)  ||  sA layer2 (+M residual)
        G2(mk(PAh, PAl, 512, c2H + (size_t)i1 * 262144, c2L + (size_t)i1 * 262144, 512,
              rcb2 + i1 * 512, Ef, 256, 256, nullptr, PBh, PBl, 512, 512), 512,
           mk(U1h, U1l, 256, s2H + (size_t)sA * 65536, s2L + (size_t)sA * 65536, 256,
              rsb2 + sA * 256, Mf, 256, 256, nullptr, U2h, U2l, 256, 256), 256);
        // pair3: big(i1) layer3 -> T0  ||  sA layer3 -> U0
        G2(mk(PBh, PBl, 512, c3H + (size_t)i1 * 131072, c3L + (size_t)i1 * 131072, 512,
              rcb3 + i1 * 256, nullptr, 0, 0, T0f, T0h, T0l, 256, 512), 256,
           mk(U2h, U2l, 256, s3H + (size_t)sA * 65536, s3L + (size_t)sA * 65536, 256,
              rsb3 + sA * 256, nullptr, 0, 0, U0f, U0h, U0l, 256, 256), 256);
        // pair4: small(i2) layer1  ||  sB layer1
        G2(mk(T0h, T0l, 256, s1H + (size_t)i2 * 65536, s1L + (size_t)i2 * 65536, 256,
              rsb1 + i2 * 256, nullptr, 0, 0, nullptr, T1h, T1l, 256, 256), 256,
           mk(U0h, U0l, 256, s1H + (size_t)sB * 65536, s1L + (size_t)sB * 65536, 256,
              rsb1 + sB * 256, nullptr, 0, 0, nullptr, U1h, U1l, 256, 256), 256);
        // pair5: small(i2) layer2 (+T0)  ||  sB layer2 (+U0)
        G2(mk(T1h, T1l, 256, s2H + (size_t)i2 * 65536, s2L + (size_t)i2 * 65536, 256,
              rsb2 + i2 * 256, T0f, 256, 256, nullptr, T2h, T2l, 256, 256), 256,
           mk(U1h, U1l, 256, s2H + (size_t)sB * 65536, s2L + (size_t)sB * 65536, 256,
              rsb2 + sB * 256, U0f, 256, 256, nullptr, U2h, U2l, 256, 256), 256);
        // pair6: small(i2) layer3 -> X2[:,:256]  ||  sB layer3 -> X2[:,256:]
        G2(mk(T2h, T2l, 256, s3H + (size_t)i2 * 65536, s3L + (size_t)i2 * 65536, 256,
              rsb3 + i2 * 256, nullptr, 0, 0, X2f, X2h, X2l, 512, 256), 256,
           mk(U2h, U2l, 256, s3H + (size_t)sB * 65536, s3L + (size_t)sB * 65536, 256,
              rsb3 + sB * 256, nullptr, 0, 0, X2f + 256, X2h + 256, X2l + 256, 512, 256), 256);

        // pair7: big(i3) layer1 (X2 -> PA)  ||  embed of next level
        GJob big1 = mk(X2h, X2l, 512, c1H + (size_t)i3 * 262144, c1L + (size_t)i3 * 262144, 512,
                       rcb1 + i3 * 512, nullptr, 0, 0, nullptr, PAh, PAl, 512, 512);
        if (l < 5) {
            G2(big1, 512,
               mk(fH + (size_t)(l + 1) * NN * 32, fL + (size_t)(l + 1) * NN * 32, 32,
                  WeH, WeL, 32, be, nullptr, 0, 0, Ef, Eh, El, 256, 32), 256);
        } else {
            G1(big1, 512);
        }
        // big(i3) layer2 (+X2 residual, full 512)
        G1(mk(PAh, PAl, 512, c2H + (size_t)i3 * 262144, c2L + (size_t)i3 * 262144, 512,
              rcb2 + i3 * 512, X2f, 512, 512, nullptr, PBh, PBl, 512, 512), 512);
        // big(i3) layer3 -> T0
        G1(mk(PBh, PBl, 512, c3H + (size_t)i3 * 131072, c3L + (size_t)i3 * 131072, 512,
              rcb3 + i3 * 256, nullptr, 0, 0, T0f, T0h, T0l, 256, 512), 256);
        // small(i4) -> out[l]
        G1(mk(T0h, T0l, 256, s1H + (size_t)i4 * 65536, s1L + (size_t)i4 * 65536, 256,
              rsb1 + i4 * 256, nullptr, 0, 0, nullptr, T1h, T1l, 256, 256), 256);
        G1(mk(T1h, T1l, 256, s2H + (size_t)i4 * 65536, s2L + (size_t)i4 * 65536, 256,
              rsb2 + i4 * 256, T0f, 256, 256, nullptr, T2h, T2l, 256, 256), 256);
        G1(mk(T2h, T2l, 256, s3H + (size_t)i4 * 65536, s3L + (size_t)i4 * 65536, 256,
              rsb3 + i4 * 256, nullptr, 0, 0,
              out + (size_t)l * NN * 256, nullptr, nullptr, 256, 256), 256);
    }
}

// round 16
// speedup vs baseline: 1.0991x; 1.0991x over previous
#include <cuda_runtime.h>
#include <cuda_bf16.h>
#include <cstdint>

// ---------------------------------------------------------------------------
// bwd_mpgnn: 6-level GNN stack. Every matmul is C = tanh(A @ W^T + b) with
// residuals folded into producer epilogues. Operands pre-split into bf16
// hi/lo planes; GEMM = cp.async(2-stage) -> ldmatrix -> mma.sync bf16x3
// (hi*hi + hi*lo + lo*hi, fp32 accumulate). 2-job batched launches.
// R16: BN=64 tile (warp tile 32x32, acc=32 regs) -> 3 CTAs/SM, occ 37.5%.
// ---------------------------------------------------------------------------

#define NN 32768
#define PAD 40                         // smem row stride in bf16 elems
#define APLANE (128 * PAD * 2)         // 10240 B (128 rows)
#define BPLANE (64 * PAD * 2)          // 5120 B  (64 rows)
#define STAGE_BYTES (2 * APLANE + 2 * BPLANE)   // 30720
#define SMEM_BYTES (2 * STAGE_BYTES)            // 61440 -> 3 CTAs/SM

typedef __nv_bfloat16 bf16;

// ---------------- weight / input split planes ------------------------------
__device__ bf16 g_WeH[8192],      g_WeL[8192];
__device__ bf16 g_fH[6 * NN * 32], g_fL[6 * NN * 32];
__device__ bf16 g_s1H[786432], g_s1L[786432];
__device__ bf16 g_s2H[786432], g_s2L[786432];
__device__ bf16 g_s3H[786432], g_s3L[786432];
__device__ bf16 g_c1H[1572864], g_c1L[1572864];
__device__ bf16 g_c2H[1572864], g_c2L[1572864];
__device__ bf16 g_c3H[786432],  g_c3L[786432];

// ---------------- activation planes ----------------------------------------
__device__ bf16 g_PAh[NN * 512], g_PAl[NN * 512];
__device__ bf16 g_PBh[NN * 512], g_PBl[NN * 512];
__device__ bf16 g_X2h[NN * 512], g_X2l[NN * 512];
__device__ bf16 g_Eh [NN * 256], g_El [NN * 256];
__device__ bf16 g_T0h[NN * 256], g_T0l[NN * 256];
__device__ bf16 g_T1h[NN * 256], g_T1l[NN * 256];
__device__ bf16 g_T2h[NN * 256], g_T2l[NN * 256];
__device__ bf16 g_Mh [NN * 256], g_Ml [NN * 256];
__device__ bf16 g_U0h[NN * 256], g_U0l[NN * 256];
__device__ bf16 g_U1h[NN * 256], g_U1l[NN * 256];
__device__ bf16 g_U2h[NN * 256], g_U2l[NN * 256];
__device__ float g_Ef [NN * 256];
__device__ float g_T0f[NN * 256];
__device__ float g_Mf [NN * 256];
__device__ float g_U0f[NN * 256];
__device__ float g_X2f[NN * 512];

// ---------------- accurate rational tanh (XLA/Eigen) -----------------------
__device__ __forceinline__ float fast_tanh(float x) {
    const float c = 7.90531110763549805f;
    x = fminf(fmaxf(x, -c), c);
    const float x2 = x * x;
    float p = fmaf(x2, -2.76076847742355e-16f, 2.00018790482477e-13f);
    p = fmaf(x2, p, -8.60467152213735e-11f);
    p = fmaf(x2, p, 5.12229709037114e-08f);
    p = fmaf(x2, p, 1.48572235717979e-05f);
    p = fmaf(x2, p, 6.37261928875436e-04f);
    p = fmaf(x2, p, 4.89352455891786e-03f);
    p = x * p;
    float q = fmaf(x2, 1.19825839466702e-06f, 1.18534705686654e-04f);
    q = fmaf(x2, q, 2.26843463243900e-03f);
    q = fmaf(x2, q, 4.89352518554385e-03f);
    return p / q;
}

// ---------------- mma / ldmatrix helpers -----------------------------------
__device__ __forceinline__ void ldm_x4(uint32_t a, uint32_t& r0, uint32_t& r1,
                                       uint32_t& r2, uint32_t& r3) {
    asm volatile("ldmatrix.sync.aligned.m8n8.x4.shared.b16 {%0,%1,%2,%3}, [%4];\n"
                 : "=r"(r0), "=r"(r1), "=r"(r2), "=r"(r3) : "r"(a));
}
__device__ __forceinline__ void mma_bf16(float* c, const uint32_t* a, const uint32_t* b) {
    asm volatile("mma.sync.aligned.m16n8k16.row.col.f32.bf16.bf16.f32 "
                 "{%0,%1,%2,%3}, {%4,%5,%6,%7}, {%8,%9}, {%0,%1,%2,%3};\n"
                 : "+f"(c[0]), "+f"(c[1]), "+f"(c[2]), "+f"(c[3])
                 : "r"(a[0]), "r"(a[1]), "r"(a[2]), "r"(a[3]), "r"(b[0]), "r"(b[1]));
}
__device__ __forceinline__ uint32_t pack2(bf16 a, bf16 b) {
    return ((uint32_t)__bfloat16_as_ushort(b) << 16) | (uint32_t)__bfloat16_as_ushort(a);
}
__device__ __forceinline__ uint32_t split_hi(float2 v, uint32_t& lo) {
    bf16 h0 = __float2bfloat16_rn(v.x), h1 = __float2bfloat16_rn(v.y);
    bf16 l0 = __float2bfloat16_rn(v.x - __bfloat162float(h0));
    bf16 l1 = __float2bfloat16_rn(v.y - __bfloat162float(h1));
    lo = pack2(l0, l1);
    return pack2(h0, h1);
}

// ---------------- job descriptor for batched GEMM launches -----------------
struct GJob {
    const bf16 *Ah, *Al, *Wh, *Wl;
    const float *bias, *R;
    float *Cf;
    bf16 *Ch, *Cl;
    int lda, ldw, ldr, Rcols, ldc, K;
};

// ---------------------------------------------------------------------------
// C = tanh(A @ W^T + bias) [+R on cols<Rcols, added after tanh]
// Two jobs per launch: blockIdx.y < split -> j0, else j1 (nBase rebased, 64-col units).
// BM=128, BN=64, BK=32, 256 threads (8 warps 4m x 2n), warp tile 32x32.
// 2-stage cp.async. 3 CTAs/SM target.
// ---------------------------------------------------------------------------
__global__ __launch_bounds__(256, 3) void gemm_tanh(GJob j0, GJob j1, int split)
{
    extern __shared__ char smem[];
    const bool s1 = (int)blockIdx.y >= split;
    const bf16* __restrict__ Ah = s1 ? j1.Ah : j0.Ah;
    const bf16* __restrict__ Al = s1 ? j1.Al : j0.Al;
    const bf16* __restrict__ Wh = s1 ? j1.Wh : j0.Wh;
    const bf16* __restrict__ Wl = s1 ? j1.Wl : j0.Wl;
    const float* __restrict__ bias = s1 ? j1.bias : j0.bias;
    const float* __restrict__ R = s1 ? j1.R : j0.R;
    float* __restrict__ Cf = s1 ? j1.Cf : j0.Cf;
    bf16* __restrict__ Ch = s1 ? j1.Ch : j0.Ch;
    bf16* __restrict__ Cl = s1 ? j1.Cl : j0.Cl;
    const int lda = s1 ? j1.lda : j0.lda;
    const int ldw = s1 ? j1.ldw : j0.ldw;
    const int ldr = s1 ? j1.ldr : j0.ldr;
    const int Rcols = s1 ? j1.Rcols : j0.Rcols;
    const int ldc = s1 ? j1.ldc : j0.ldc;
    const int K  = s1 ? j1.K : j0.K;

    const int tid  = threadIdx.x;
    const int lane = tid & 31;
    const int wid  = tid >> 5;
    const int wm   = wid >> 1;   // 0..3
    const int wn   = wid & 1;    // 0..1
    const int mBase = blockIdx.x * 128;
    const int nBase = (s1 ? (int)blockIdx.y - split : (int)blockIdx.y) * 64;
    const uint32_t sb = (uint32_t)__cvta_generic_to_shared(smem);

    float acc[2][4][4];
#pragma unroll
    for (int i = 0; i < 2; i++)
#pragma unroll
        for (int j = 0; j < 4; j++)
#pragma unroll
            for (int k = 0; k < 4; k++) acc[i][j][k] = 0.f;

    const int T = K >> 5;
    const int seg   = tid & 3;           // 16B segment
    const int rhalf = tid >> 2;          // 0..63

    auto issue = [&](int t) {
        const int k0 = (t << 5) + seg * 8;
        const uint32_t stb = sb + (uint32_t)((t & 1) * STAGE_BYTES);
        // A planes: 2 planes x 128 rows
#pragma unroll
        for (int i = 0; i < 4; i++) {
            const int plane = i >> 1;                 // 0:Ah 1:Al
            const int row   = (i & 1) * 64 + rhalf;   // 0..127
            const uint32_t dst = stb + (uint32_t)(plane * APLANE + row * (PAD * 2) + seg * 16);
            const bf16* src = (plane ? Al : Ah) + (size_t)(mBase + row) * lda + k0;
            asm volatile("cp.async.cg.shared.global [%0], [%1], 16;\n" :: "r"(dst), "l"(src));
        }
        // B planes: 2 planes x 64 rows
#pragma unroll
        for (int p = 0; p < 2; p++) {
            const uint32_t dst = stb + (uint32_t)(2 * APLANE + p * BPLANE + rhalf * (PAD * 2) + seg * 16);
            const bf16* src = (p ? Wl : Wh) + (size_t)(nBase + rhalf) * ldw + k0;
            asm volatile("cp.async.cg.shared.global [%0], [%1], 16;\n" :: "r"(dst), "l"(src));
        }
    };

    const int r16  = ((lane >> 3) & 1) * 8 + (lane & 7);
    const int kofA = (lane >> 4) * 8;
    const int bRow = ((lane >> 4) & 1) * 8 + (lane & 7);
    const int kofB = ((lane >> 3) & 1) * 8;

    auto compute = [&](int s) {
        const uint32_t ab  = sb + (uint32_t)(s * STAGE_BYTES);
        const uint32_t abl = ab + APLANE;
        const uint32_t bbh = ab + 2 * APLANE;
        const uint32_t bbl = bbh + BPLANE;
#pragma unroll
        for (int ks = 0; ks < 2; ks++) {
            uint32_t a1[2][4], a2[2][4], bh[4][2], bl[4][2];
            // front-load all fragments for this ks
#pragma unroll
            for (int mf = 0; mf < 2; mf++) {
                const uint32_t addr = ab +
                    (uint32_t)(((wm * 32 + mf * 16 + r16) * PAD + ks * 16 + kofA) * 2);
                ldm_x4(addr, a1[mf][0], a1[mf][1], a1[mf][2], a1[mf][3]);
            }
#pragma unroll
            for (int p = 0; p < 2; p++) {
                const uint32_t addr = bbh +
                    (uint32_t)(((wn * 32 + p * 16 + bRow) * PAD + ks * 16 + kofB) * 2);
                ldm_x4(addr, bh[2 * p][0], bh[2 * p][1], bh[2 * p + 1][0], bh[2 * p + 1][1]);
            }
#pragma unroll
            for (int p = 0; p < 2; p++) {
                const uint32_t addr = bbl +
                    (uint32_t)(((wn * 32 + p * 16 + bRow) * PAD + ks * 16 + kofB) * 2);
                ldm_x4(addr, bl[2 * p][0], bl[2 * p][1], bl[2 * p + 1][0], bl[2 * p + 1][1]);
            }
#pragma unroll
            for (int mf = 0; mf < 2; mf++) {
                const uint32_t addr = abl +
                    (uint32_t)(((wm * 32 + mf * 16 + r16) * PAD + ks * 16 + kofA) * 2);
                ldm_x4(addr, a2[mf][0], a2[mf][1], a2[mf][2], a2[mf][3]);
            }
            // contiguous MMA bursts
#pragma unroll
            for (int mf = 0; mf < 2; mf++)
#pragma unroll
                for (int nf = 0; nf < 4; nf++) mma_bf16(acc[mf][nf], a1[mf], bh[nf]);
#pragma unroll
            for (int mf = 0; mf < 2; mf++)
#pragma unroll
                for (int nf = 0; nf < 4; nf++) mma_bf16(acc[mf][nf], a1[mf], bl[nf]);
#pragma unroll
            for (int mf = 0; mf < 2; mf++)
#pragma unroll
                for (int nf = 0; nf < 4; nf++) mma_bf16(acc[mf][nf], a2[mf], bh[nf]);
        }
    };

    issue(0);
    asm volatile("cp.async.commit_group;\n" ::: "memory");
    for (int t = 0; t < T; t++) {
        asm volatile("cp.async.wait_group 0;\n" ::: "memory");
        __syncthreads();
        if (t + 1 < T) {
            issue(t + 1);
            asm volatile("cp.async.commit_group;\n" ::: "memory");
        }
        compute(t & 1);
    }

    // epilogue: bias + tanh (+residual), write fp32 and/or split planes
#pragma unroll
    for (int mf = 0; mf < 2; mf++) {
        const int r0 = mBase + wm * 32 + mf * 16 + (lane >> 2);
#pragma unroll
        for (int nf = 0; nf < 4; nf++) {
            const int c0 = nBase + wn * 32 + nf * 8 + (lane & 3) * 2;
            const float b0 = __ldg(bias + c0), b1 = __ldg(bias + c0 + 1);
            float2 v0 = make_float2(fast_tanh(acc[mf][nf][0] + b0),
                                    fast_tanh(acc[mf][nf][1] + b1));
            float2 v1 = make_float2(fast_tanh(acc[mf][nf][2] + b0),
                                    fast_tanh(acc[mf][nf][3] + b1));
            if (R != nullptr && c0 < Rcols) {
                const float2 ra = *(const float2*)(R + (size_t)r0 * ldr + c0);
                const float2 rb = *(const float2*)(R + (size_t)(r0 + 8) * ldr + c0);
                v0.x += ra.x; v0.y += ra.y;
                v1.x += rb.x; v1.y += rb.y;
            }
            const size_t o0 = (size_t)r0 * ldc + c0;
            const size_t o1 = (size_t)(r0 + 8) * ldc + c0;
            if (Cf != nullptr) {
                *(float2*)(Cf + o0) = v0;
                *(float2*)(Cf + o1) = v1;
            }
            if (Ch != nullptr) {
                uint32_t lo0, lo1;
                const uint32_t hi0 = split_hi(v0, lo0);
                const uint32_t hi1 = split_hi(v1, lo1);
                *(uint32_t*)(Ch + o0) = hi0;  *(uint32_t*)(Cl + o0) = lo0;
                *(uint32_t*)(Ch + o1) = hi1;  *(uint32_t*)(Cl + o1) = lo1;
            }
        }
    }
}

// ---------------- fused fp32 -> bf16 hi/lo split over 8 tensors ------------
struct SplitJobs {
    const float* src[8];
    bf16* h[8];
    bf16* l[8];
    int n4[8];
    int boff[8];
};
__global__ __launch_bounds__(256) void split_all(SplitJobs J) {
    const int b = blockIdx.x;
    int j = 0;
#pragma unroll
    for (int i = 1; i < 8; i++)
        if (b >= J.boff[i]) j = i;
    const int i4 = (b - J.boff[j]) * 256 + threadIdx.x;
    if (i4 >= J.n4[j]) return;
    const float4 v = *(const float4*)(J.src[j] + (size_t)i4 * 4);
    uint32_t lo0, lo1;
    const uint32_t hi0 = split_hi(make_float2(v.x, v.y), lo0);
    const uint32_t hi1 = split_hi(make_float2(v.z, v.w), lo1);
    *(uint2*)(J.h[j] + (size_t)i4 * 4) = make_uint2(hi0, hi1);
    *(uint2*)(J.l[j] + (size_t)i4 * 4) = make_uint2(lo0, lo1);
}

// msgs[n,:] = sum_{k<8} src[idx[n,k], :] ; writes fp32 + split planes
__global__ __launch_bounds__(256) void gather_sum(
    const float* __restrict__ src, const int* __restrict__ idx,
    float* __restrict__ dstf, bf16* __restrict__ dsth, bf16* __restrict__ dstl)
{
    const int node = blockIdx.x * 4 + (threadIdx.x >> 6);
    const int lane = threadIdx.x & 63;
    const int* ip = idx + node * 8;
    float4 s = make_float4(0.f, 0.f, 0.f, 0.f);
#pragma unroll
    for (int k = 0; k < 8; k++) {
        const float4 v = *(const float4*)(src + (size_t)ip[k] * 256 + lane * 4);
        s.x += v.x; s.y += v.y; s.z += v.z; s.w += v.w;
    }
    const size_t o = (size_t)node * 256 + lane * 4;
    *(float4*)(dstf + o) = s;
    uint32_t lo0, lo1;
    const uint32_t hi0 = split_hi(make_float2(s.x, s.y), lo0);
    const uint32_t hi1 = split_hi(make_float2(s.z, s.w), lo1);
    *(uint2*)(dsth + o) = make_uint2(hi0, hi1);
    *(uint2*)(dstl + o) = make_uint2(lo0, lo1);
}

extern "C" void kernel_launch(void* const* d_in, const int* in_sizes, int n_in,
                              void* d_out, int out_size)
{
    const float* feats = (const float*)d_in[0];
    const int*   pred  = (const int*)  d_in[1];
    const float* WeF   = (const float*)d_in[2];
    const float* be    = (const float*)d_in[3];
    const float* rsW1  = (const float*)d_in[4];
    const float* rsb1  = (const float*)d_in[5];
    const float* rsW2  = (const float*)d_in[6];
    const float* rsb2  = (const float*)d_in[7];
    const float* rsW3  = (const float*)d_in[8];
    const float* rsb3  = (const float*)d_in[9];
    const float* rcW1  = (const float*)d_in[10];
    const float* rcb1  = (const float*)d_in[11];
    const float* rcW2  = (const float*)d_in[12];
    const float* rcb2  = (const float*)d_in[13];
    const float* rcW3  = (const float*)d_in[14];
    const float* rcb3  = (const float*)d_in[15];
    float* out = (float*)d_out;

    bf16 *WeH,*WeL,*fH,*fL,*s1H,*s1L,*s2H,*s2L,*s3H,*s3L,*c1H,*c1L,*c2H,*c2L,*c3H,*c3L;
    bf16 *PAh,*PAl,*PBh,*PBl,*X2h,*X2l,*Eh,*El,*T0h,*T0l,*T1h,*T1l,*T2h,*T2l,*Mh,*Ml;
    bf16 *U0h,*U0l,*U1h,*U1l,*U2h,*U2l;
    float *Ef,*T0f,*Mf,*U0f,*X2f;
    cudaGetSymbolAddress((void**)&WeH, g_WeH); cudaGetSymbolAddress((void**)&WeL, g_WeL);
    cudaGetSymbolAddress((void**)&fH,  g_fH);  cudaGetSymbolAddress((void**)&fL,  g_fL);
    cudaGetSymbolAddress((void**)&s1H, g_s1H); cudaGetSymbolAddress((void**)&s1L, g_s1L);
    cudaGetSymbolAddress((void**)&s2H, g_s2H); cudaGetSymbolAddress((void**)&s2L, g_s2L);
    cudaGetSymbolAddress((void**)&s3H, g_s3H); cudaGetSymbolAddress((void**)&s3L, g_s3L);
    cudaGetSymbolAddress((void**)&c1H, g_c1H); cudaGetSymbolAddress((void**)&c1L, g_c1L);
    cudaGetSymbolAddress((void**)&c2H, g_c2H); cudaGetSymbolAddress((void**)&c2L, g_c2L);
    cudaGetSymbolAddress((void**)&c3H, g_c3H); cudaGetSymbolAddress((void**)&c3L, g_c3L);
    cudaGetSymbolAddress((void**)&PAh, g_PAh); cudaGetSymbolAddress((void**)&PAl, g_PAl);
    cudaGetSymbolAddress((void**)&PBh, g_PBh); cudaGetSymbolAddress((void**)&PBl, g_PBl);
    cudaGetSymbolAddress((void**)&X2h, g_X2h); cudaGetSymbolAddress((void**)&X2l, g_X2l);
    cudaGetSymbolAddress((void**)&Eh,  g_Eh);  cudaGetSymbolAddress((void**)&El,  g_El);
    cudaGetSymbolAddress((void**)&T0h, g_T0h); cudaGetSymbolAddress((void**)&T0l, g_T0l);
    cudaGetSymbolAddress((void**)&T1h, g_T1h); cudaGetSymbolAddress((void**)&T1l, g_T1l);
    cudaGetSymbolAddress((void**)&T2h, g_T2h); cudaGetSymbolAddress((void**)&T2l, g_T2l);
    cudaGetSymbolAddress((void**)&Mh,  g_Mh);  cudaGetSymbolAddress((void**)&Ml,  g_Ml);
    cudaGetSymbolAddress((void**)&U0h, g_U0h); cudaGetSymbolAddress((void**)&U0l, g_U0l);
    cudaGetSymbolAddress((void**)&U1h, g_U1h); cudaGetSymbolAddress((void**)&U1l, g_U1l);
    cudaGetSymbolAddress((void**)&U2h, g_U2h); cudaGetSymbolAddress((void**)&U2l, g_U2l);
    cudaGetSymbolAddress((void**)&Ef,  g_Ef);  cudaGetSymbolAddress((void**)&T0f, g_T0f);
    cudaGetSymbolAddress((void**)&Mf,  g_Mf);  cudaGetSymbolAddress((void**)&U0f, g_U0f);
    cudaGetSymbolAddress((void**)&X2f, g_X2f);

    cudaFuncSetAttribute(gemm_tanh, cudaFuncAttributeMaxDynamicSharedMemorySize, SMEM_BYTES);

    // one fused split launch for all weights + feats
    {
        SplitJobs J;
        const float* srcs[8] = {WeF, feats, rsW1, rsW2, rsW3, rcW1, rcW2, rcW3};
        bf16* hs[8] = {WeH, fH, s1H, s2H, s3H, c1H, c2H, c3H};
        bf16* ls[8] = {WeL, fL, s1L, s2L, s3L, c1L, c2L, c3L};
        const int ns[8] = {8192, 6 * NN * 32, 786432, 786432, 786432,
                           1572864, 1572864, 786432};
        int off = 0;
        for (int i = 0; i < 8; i++) {
            J.src[i] = srcs[i]; J.h[i] = hs[i]; J.l[i] = ls[i];
            J.n4[i] = ns[i] / 4; J.boff[i] = off;
            off += (J.n4[i] + 255) / 256;
        }
        split_all<<<off, 256>>>(J);
    }

    auto mk = [](const bf16* Ah, const bf16* Al, int lda,
                 const bf16* Wh, const bf16* Wl, int ldw,
                 const float* b, const float* R, int ldr, int Rcols,
                 float* Cf, bf16* Ch, bf16* Cl, int ldc, int K) {
        GJob j;
        j.Ah = Ah; j.Al = Al; j.Wh = Wh; j.Wl = Wl;
        j.bias = b; j.R = R; j.Cf = Cf; j.Ch = Ch; j.Cl = Cl;
        j.lda = lda; j.ldw = ldw; j.ldr = ldr; j.Rcols = Rcols; j.ldc = ldc; j.K = K;
        return j;
    };
    auto G1 = [&](GJob a, int Na) {
        dim3 grid(NN / 128, Na / 64);
        gemm_tanh<<<grid, 256, SMEM_BYTES>>>(a, a, Na / 64);
    };
    auto G2 = [&](GJob a, int Na, GJob b, int Nb) {
        dim3 grid(NN / 128, (Na + Nb) / 64);
        gemm_tanh<<<grid, 256, SMEM_BYTES>>>(a, b, Na / 64);
    };

    // boot: out[0] = embed(feats0)  ||  E = embed(feats1)
    G2(mk(fH, fL, 32, WeH, WeL, 32, be, nullptr, 0, 0,
          out, nullptr, nullptr, 256, 32), 256,
       mk(fH + (size_t)NN * 32, fL + (size_t)NN * 32, 32, WeH, WeL, 32, be,
          nullptr, 0, 0, Ef, Eh, El, 256, 32), 256);

    for (int l = 1; l < 6; l++) {
        const int d  = (l - 1 < 2) ? (l - 1) : 2;
        const int i1 = 3 + d, i2 = 9 + d, i3 = d, i4 = 6 + d;
        const int sA = 2 * d, sB = 2 * d + 1;

        gather_sum<<<NN / 4, 256>>>(out + (size_t)(l - 1) * NN * 256,
                                    pred + (size_t)(l - 1) * NN * 8, Mf, Mh, Ml);

        // pair1: big(i1) layer1 (E -> PA, K=256 zero-half skipped)  ||  sA layer1
        G2(mk(Eh, El, 256, c1H + (size_t)i1 * 262144, c1L + (size_t)i1 * 262144, 512,
              rcb1 + i1 * 512, nullptr, 0, 0, nullptr, PAh, PAl, 512, 256), 512,
           mk(Mh, Ml, 256, s1H + (size_t)sA * 65536, s1L + (size_t)sA * 65536, 256,
              rsb1 + sA * 256, nullptr, 0, 0, nullptr, U1h, U1l, 256, 256), 256);
        // pair2: big(i1) layer2 (+E residual)  ||  sA layer2 (+M residual)
        G2(mk(PAh, PAl, 512, c2H + (size_t)i1 * 262144, c2L + (size_t)i1 * 262144, 512,
              rcb2 + i1 * 512, Ef, 256, 256, nullptr, PBh, PBl, 512, 512), 512,
           mk(U1h, U1l, 256, s2H + (size_t)sA * 65536, s2L + (size_t)sA * 65536, 256,
              rsb2 + sA * 256, Mf, 256, 256, nullptr, U2h, U2l, 256, 256), 256);
        // pair3: big(i1) layer3 -> T0  ||  sA layer3 -> U0
        G2(mk(PBh, PBl, 512, c3H + (size_t)i1 * 131072, c3L + (size_t)i1 * 131072, 512,
              rcb3 + i1 * 256, nullptr, 0, 0, T0f, T0h, T0l, 256, 512), 256,
           mk(U2h, U2l, 256, s3H + (size_t)sA * 65536, s3L + (size_t)sA * 65536, 256,
              rsb3 + sA * 256, nullptr, 0, 0, U0f, U0h, U0l, 256, 256), 256);
        // pair4: small(i2) layer1  ||  sB layer1
        G2(mk(T0h, T0l, 256, s1H + (size_t)i2 * 65536, s1L + (size_t)i2 * 65536, 256,
              rsb1 + i2 * 256, nullptr, 0, 0, nullptr, T1h, T1l, 256, 256), 256,
           mk(U0h, U0l, 256, s1H + (size_t)sB * 65536, s1L + (size_t)sB * 65536, 256,
              rsb1 + sB * 256, nullptr, 0, 0, nullptr, U1h, U1l, 256, 256), 256);
        // pair5: small(i2) layer2 (+T0)  ||  sB layer2 (+U0)
        G2(mk(T1h, T1l, 256, s2H + (size_t)i2 * 65536, s2L + (size_t)i2 * 65536, 256,
              rsb2 + i2 * 256, T0f, 256, 256, nullptr, T2h, T2l, 256, 256), 256,
           mk(U1h, U1l, 256, s2H + (size_t)sB * 65536, s2L + (size_t)sB * 65536, 256,
              rsb2 + sB * 256, U0f, 256, 256, nullptr, U2h, U2l, 256, 256), 256);
        // pair6: small(i2) layer3 -> X2[:,:256]  ||  sB layer3 -> X2[:,256:]
        G2(mk(T2h, T2l, 256, s3H + (size_t)i2 * 65536, s3L + (size_t)i2 * 65536, 256,
              rsb3 + i2 * 256, nullptr, 0, 0, X2f, X2h, X2l, 512, 256), 256,
           mk(U2h, U2l, 256, s3H + (size_t)sB * 65536, s3L + (size_t)sB * 65536, 256,
              rsb3 + sB * 256, nullptr, 0, 0, X2f + 256, X2h + 256, X2l + 256, 512, 256), 256);

        // pair7: big(i3) layer1 (X2 -> PA)  ||  embed of next level
        GJob big1 = mk(X2h, X2l, 512, c1H + (size_t)i3 * 262144, c1L + (size_t)i3 * 262144, 512,
                       rcb1 + i3 * 512, nullptr, 0, 0, nullptr, PAh, PAl, 512, 512);
        if (l < 5) {
            G2(big1, 512,
               mk(fH + (size_t)(l + 1) * NN * 32, fL + (size_t)(l + 1) * NN * 32, 32,
                  WeH, WeL, 32, be, nullptr, 0, 0, Ef, Eh, El, 256, 32), 256);
        } else {
            G1(big1, 512);
        }
        // big(i3) layer2 (+X2 residual, full 512)
        G1(mk(PAh, PAl, 512, c2H + (size_t)i3 * 262144, c2L + (size_t)i3 * 262144, 512,
              rcb2 + i3 * 512, X2f, 512, 512, nullptr, PBh, PBl, 512, 512), 512);
        // big(i3) layer3 -> T0
        G1(mk(PBh, PBl, 512, c3H + (size_t)i3 * 131072, c3L + (size_t)i3 * 131072, 512,
              rcb3 + i3 * 256, nullptr, 0, 0, T0f, T0h, T0l, 256, 512), 256);
        // small(i4) -> out[l]
        G1(mk(T0h, T0l, 256, s1H + (size_t)i4 * 65536, s1L + (size_t)i4 * 65536, 256,
              rsb1 + i4 * 256, nullptr, 0, 0, nullptr, T1h, T1l, 256, 256), 256);
        G1(mk(T1h, T1l, 256, s2H + (size_t)i4 * 65536, s2L + (size_t)i4 * 65536, 256,
              rsb2 + i4 * 256, T0f, 256, 256, nullptr, T2h, T2l, 256, 256), 256);
        G1(mk(T2h, T2l, 256, s3H + (size_t)i4 * 65536, s3L + (size_t)i4 * 65536, 256,
              rsb3 + i4 * 256, nullptr, 0, 0,
              out + (size_t)l * NN * 256, nullptr, nullptr, 256, 256), 256);
    }
}